// round 5
// baseline (speedup 1.0000x reference)
#include <cuda_runtime.h>

// EmergentNeuralNetwork collapsed form: out = tanh(h_star @ w_ho - 0.5)
//   h_star[:, j<3]  = tanh(x @ w_in[:, j] - thr_h[j])
//   h_star[:, j>=3] = tanh(-thr_h[j])  (batch-constant, folded in epilogue)
//
// Inputs: x f32[8192,4096], w_in f32[4096,3], w_ho f32[64,8], thr_h f32[64]
// Output: f32[8192,8]
//
// Strategy: cp.async.cg deep pipeline. Each CTA owns 8 rows (128 KB of x),
// issues ALL of it as 4 commit-groups of 16B cp.asyncs up front (no dest
// registers -> MLP decoupled from register file), then drains stage by stage.
// Thread t only consumes smem it wrote itself -> no barriers in the mainloop.

#define TPB 256
#define RPB 8
#define COLS 4096
#define BATCH 8192
#define OUTS 8
#define STAGES 4
#define STAGE_F4 (RPB * TPB)                 // 2048 float4 = 32 KB per stage
#define SMEM_BYTES (STAGES * STAGE_F4 * 16)  // 128 KB

template <int N>
__device__ __forceinline__ void cp_async_wait_group() {
    asm volatile("cp.async.wait_group %0;" :: "n"(N) : "memory");
}

__global__ __launch_bounds__(TPB, 1)
void enn_kernel(const float* __restrict__ x,
                const float* __restrict__ w_in,
                const float* __restrict__ w_ho,
                const float* __restrict__ thr_h,
                float* __restrict__ out)
{
    extern __shared__ float4 sx[];       // [STAGES][RPB][TPB]
    __shared__ float s_part[8][RPB][3];  // [warp][row][hidden]
    __shared__ float s_tanh[61];         // tanh(-thr_h[j]) for j=3..63

    const int t    = threadIdx.x;
    const int warp = t >> 5;
    const int lane = t & 31;
    const size_t row0 = (size_t)blockIdx.x * RPB;

    const unsigned sbase = (unsigned)__cvta_generic_to_shared(sx);

    // ---- issue the CTA's entire x footprint: 4 stages x 8 rows x 16B/thread
    #pragma unroll
    for (int s = 0; s < STAGES; s++) {
        #pragma unroll
        for (int r = 0; r < RPB; r++) {
            const unsigned daddr = sbase + (((s * RPB + r) * TPB + t) << 4);
            const float* gp = x + (row0 + r) * COLS + s * 1024 + t * 4;
            asm volatile("cp.async.cg.shared.global [%0], [%1], 16;"
                         :: "r"(daddr), "l"(gp) : "memory");
        }
        asm volatile("cp.async.commit_group;" ::: "memory");
    }

    // ---- latency-hidden prologue work (overlaps the cp.async stream)
    if (t < 61)
        s_tanh[t] = tanhf(-thr_h[t + 3]);

    // w_in register cache: 12 floats per column-group, 4 groups
    float4 wreg[STAGES][3];
    #pragma unroll
    for (int c = 0; c < STAGES; c++) {
        const int col = c * 1024 + t * 4;
        const float4* wp = reinterpret_cast<const float4*>(w_in + (size_t)col * 3);
        wreg[c][0] = __ldg(wp + 0);
        wreg[c][1] = __ldg(wp + 1);
        wreg[c][2] = __ldg(wp + 2);
    }

    float acc[RPB][3];
    #pragma unroll
    for (int r = 0; r < RPB; r++) {
        acc[r][0] = 0.f; acc[r][1] = 0.f; acc[r][2] = 0.f;
    }

    // ---- drain stages; each thread reads only what it wrote (no barriers)
    #pragma unroll
    for (int s = 0; s < STAGES; s++) {
        switch (s) {
            case 0: cp_async_wait_group<3>(); break;
            case 1: cp_async_wait_group<2>(); break;
            case 2: cp_async_wait_group<1>(); break;
            default: cp_async_wait_group<0>(); break;
        }
        const float4 w0 = wreg[s][0], w1 = wreg[s][1], w2 = wreg[s][2];
        #pragma unroll
        for (int r = 0; r < RPB; r++) {
            const float4 xv = sx[(s * RPB + r) * TPB + t];
            // 12-float w group maps: element e -> (col + e/3, hidden j = e%3)
            acc[r][0] = fmaf(xv.x, w0.x, acc[r][0]);
            acc[r][1] = fmaf(xv.x, w0.y, acc[r][1]);
            acc[r][2] = fmaf(xv.x, w0.z, acc[r][2]);
            acc[r][0] = fmaf(xv.y, w0.w, acc[r][0]);
            acc[r][1] = fmaf(xv.y, w1.x, acc[r][1]);
            acc[r][2] = fmaf(xv.y, w1.y, acc[r][2]);
            acc[r][0] = fmaf(xv.z, w1.z, acc[r][0]);
            acc[r][1] = fmaf(xv.z, w1.w, acc[r][1]);
            acc[r][2] = fmaf(xv.z, w2.x, acc[r][2]);
            acc[r][0] = fmaf(xv.w, w2.y, acc[r][0]);
            acc[r][1] = fmaf(xv.w, w2.z, acc[r][1]);
            acc[r][2] = fmaf(xv.w, w2.w, acc[r][2]);
        }
    }

    // ---- single butterfly reduction over all 24 accumulators
    #pragma unroll
    for (int off = 16; off > 0; off >>= 1) {
        #pragma unroll
        for (int r = 0; r < RPB; r++) {
            acc[r][0] += __shfl_xor_sync(0xFFFFFFFFu, acc[r][0], off);
            acc[r][1] += __shfl_xor_sync(0xFFFFFFFFu, acc[r][1], off);
            acc[r][2] += __shfl_xor_sync(0xFFFFFFFFu, acc[r][2], off);
        }
    }
    if (lane == 0) {
        #pragma unroll
        for (int r = 0; r < RPB; r++) {
            s_part[warp][r][0] = acc[r][0];
            s_part[warp][r][1] = acc[r][1];
            s_part[warp][r][2] = acc[r][2];
        }
    }
    __syncthreads();

    // ---- 64 threads: one (row, output) pair each
    if (t < RPB * OUTS) {
        const int r = t >> 3;
        const int o = t & 7;
        float s0 = 0.f, s1 = 0.f, s2 = 0.f;
        #pragma unroll
        for (int w = 0; w < 8; w++) {
            s0 += s_part[w][r][0];
            s1 += s_part[w][r][1];
            s2 += s_part[w][r][2];
        }
        // base[o]: contribution of the 61 disconnected hiddens
        float v = -0.5f;
        #pragma unroll 1
        for (int j = 0; j < 61; j++)
            v = fmaf(s_tanh[j], w_ho[(j + 3) * OUTS + o], v);
        const float h0 = tanhf(s0 - thr_h[0]);
        const float h1 = tanhf(s1 - thr_h[1]);
        const float h2 = tanhf(s2 - thr_h[2]);
        v = fmaf(h0, w_ho[0 * OUTS + o], v);
        v = fmaf(h1, w_ho[1 * OUTS + o], v);
        v = fmaf(h2, w_ho[2 * OUTS + o], v);
        out[(row0 + r) * OUTS + o] = tanhf(v);
    }
}

extern "C" void kernel_launch(void* const* d_in, const int* in_sizes, int n_in,
                              void* d_out, int out_size)
{
    const float* x     = (const float*)d_in[0];
    const float* w_in  = (const float*)d_in[1];
    const float* w_ho  = (const float*)d_in[2];
    const float* thr_h = (const float*)d_in[3];
    float* out = (float*)d_out;

    // idempotent; no allocation. Needed for 128 KB dynamic smem.
    cudaFuncSetAttribute(enn_kernel,
                         cudaFuncAttributeMaxDynamicSharedMemorySize, SMEM_BYTES);

    enn_kernel<<<BATCH / RPB, TPB, SMEM_BYTES>>>(x, w_in, w_ho, thr_h, out);
}

// round 7
// speedup vs baseline: 1.5280x; 1.5280x over previous
#include <cuda_runtime.h>

// EmergentNeuralNetwork collapsed form: out = tanh(h_star @ w_ho - 0.5)
//   h_star[:, j<3]  = tanh(x @ w_in[:, j] - thr_h[j])
//   h_star[:, j>=3] = tanh(-thr_h[j])  (batch-constant, folded once per CTA)
//
// Inputs: x f32[8192,4096], w_in f32[4096,3], w_ho f32[64,8], thr_h f32[64]
// Output: f32[8192,8]
//
// Persistent-CTA streaming: 444 CTAs grid-stride over 2048 blocks of 4 rows.
// Register double-buffered loads keep the LSU issuing every iteration; the
// per-block reduction tail is tiny and covered by 3 CTAs/SM.

#define TPB 256
#define RPB 4
#define COLS 4096
#define BATCH 8192
#define OUTS 8
#define NBLK (BATCH / RPB)   // 2048
#define GRID 444             // ~3 CTAs per SM on 148 SMs

__global__ __launch_bounds__(TPB, 3)
void enn_kernel(const float* __restrict__ x,
                const float* __restrict__ w_in,
                const float* __restrict__ w_ho,
                const float* __restrict__ thr_h,
                float* __restrict__ out)
{
    __shared__ float s_part[8][RPB][3];  // [warp][row][hidden]
    __shared__ float s_base[OUTS];
    __shared__ float s_tanh[61];

    const int t    = threadIdx.x;
    const int warp = t >> 5;
    const int lane = t & 31;

    // ---- once per CTA: fold the 61 disconnected hiddens into base[o]
    if (t < 61)
        s_tanh[t] = tanhf(-thr_h[t + 3]);
    __syncthreads();
    if (t < OUTS) {
        float b = -0.5f;
        #pragma unroll
        for (int j = 0; j < 61; j++)
            b = fmaf(s_tanh[j], __ldg(w_ho + (j + 3) * OUTS + t), b);
        s_base[t] = b;
    }
    const float th0 = __ldg(thr_h + 0);
    const float th1 = __ldg(thr_h + 1);
    const float th2 = __ldg(thr_h + 2);

    // ---- persistent loop over row-blocks
    for (int blk = blockIdx.x; blk < NBLK; blk += GRID) {
        const size_t row0 = (size_t)blk * RPB;
        const float4* xrow[RPB];
        #pragma unroll
        for (int r = 0; r < RPB; r++)
            xrow[r] = reinterpret_cast<const float4*>(x + (row0 + r) * COLS);

        float acc[RPB][3];
        #pragma unroll
        for (int r = 0; r < RPB; r++) {
            acc[r][0] = 0.f; acc[r][1] = 0.f; acc[r][2] = 0.f;
        }

        // double-buffered x loads: preload group 0
        float4 xv[2][RPB];
        #pragma unroll
        for (int r = 0; r < RPB; r++)
            xv[0][r] = __ldcs(xrow[r] + t);

        #pragma unroll
        for (int c = 0; c < 4; c++) {
            // issue next group's loads BEFORE consuming current group
            if (c < 3) {
                const int nb = (c + 1) & 1;
                const int noff = (c + 1) * 256 + t;
                #pragma unroll
                for (int r = 0; r < RPB; r++)
                    xv[nb][r] = __ldcs(xrow[r] + noff);
            }
            // 12-float w group for columns {c*1024 + 4t .. +3}  (L1/L2-hot)
            const float4* wp = reinterpret_cast<const float4*>(
                w_in + ((size_t)(c * 1024) + t * 4) * 3);
            const float4 w0 = __ldg(wp + 0);
            const float4 w1 = __ldg(wp + 1);
            const float4 w2 = __ldg(wp + 2);

            #pragma unroll
            for (int r = 0; r < RPB; r++) {
                const float4 v = xv[c & 1][r];
                // element e of the 12-float group -> (col + e/3, hidden e%3)
                acc[r][0] = fmaf(v.x, w0.x, acc[r][0]);
                acc[r][1] = fmaf(v.x, w0.y, acc[r][1]);
                acc[r][2] = fmaf(v.x, w0.z, acc[r][2]);
                acc[r][0] = fmaf(v.y, w0.w, acc[r][0]);
                acc[r][1] = fmaf(v.y, w1.x, acc[r][1]);
                acc[r][2] = fmaf(v.y, w1.y, acc[r][2]);
                acc[r][0] = fmaf(v.z, w1.z, acc[r][0]);
                acc[r][1] = fmaf(v.z, w1.w, acc[r][1]);
                acc[r][2] = fmaf(v.z, w2.x, acc[r][2]);
                acc[r][0] = fmaf(v.w, w2.y, acc[r][0]);
                acc[r][1] = fmaf(v.w, w2.z, acc[r][1]);
                acc[r][2] = fmaf(v.w, w2.w, acc[r][2]);
            }
        }

        // butterfly reduce the 12 accumulators across the warp
        #pragma unroll
        for (int off = 16; off > 0; off >>= 1) {
            #pragma unroll
            for (int r = 0; r < RPB; r++) {
                acc[r][0] += __shfl_xor_sync(0xFFFFFFFFu, acc[r][0], off);
                acc[r][1] += __shfl_xor_sync(0xFFFFFFFFu, acc[r][1], off);
                acc[r][2] += __shfl_xor_sync(0xFFFFFFFFu, acc[r][2], off);
            }
        }
        if (lane == 0) {
            #pragma unroll
            for (int r = 0; r < RPB; r++) {
                s_part[warp][r][0] = acc[r][0];
                s_part[warp][r][1] = acc[r][1];
                s_part[warp][r][2] = acc[r][2];
            }
        }
        __syncthreads();

        // 32 threads: one (row, output) pair each
        if (t < RPB * OUTS) {
            const int r = t >> 3;
            const int o = t & 7;
            float s0 = 0.f, s1 = 0.f, s2 = 0.f;
            #pragma unroll
            for (int w = 0; w < 8; w++) {
                s0 += s_part[w][r][0];
                s1 += s_part[w][r][1];
                s2 += s_part[w][r][2];
            }
            const float h0 = tanhf(s0 - th0);
            const float h1 = tanhf(s1 - th1);
            const float h2 = tanhf(s2 - th2);
            float v = s_base[o];
            v = fmaf(h0, __ldg(w_ho + 0 * OUTS + o), v);
            v = fmaf(h1, __ldg(w_ho + 1 * OUTS + o), v);
            v = fmaf(h2, __ldg(w_ho + 2 * OUTS + o), v);
            out[(row0 + r) * OUTS + o] = tanhf(v);
        }
        __syncthreads();   // protect s_part before next block iteration
    }
}

extern "C" void kernel_launch(void* const* d_in, const int* in_sizes, int n_in,
                              void* d_out, int out_size)
{
    const float* x     = (const float*)d_in[0];
    const float* w_in  = (const float*)d_in[1];
    const float* w_ho  = (const float*)d_in[2];
    const float* thr_h = (const float*)d_in[3];
    float* out = (float*)d_out;

    enn_kernel<<<GRID, TPB>>>(x, w_in, w_ho, thr_h, out);
}

// round 9
// speedup vs baseline: 1.5294x; 1.0009x over previous
#include <cuda_runtime.h>

// EmergentNeuralNetwork collapsed form: out = tanh(h_star @ w_ho - 0.5)
//   h_star[:, j<3]  = tanh(x @ w_in[:, j] - thr_h[j])
//   h_star[:, j>=3] = tanh(-thr_h[j])  (batch-constant, folded once per CTA)
//
// Inputs: x f32[8192,4096], w_in f32[4096,3], w_ho f32[64,8], thr_h f32[64]
// Output: f32[8192,8]
//
// Persistent-CTA streaming, deepened: 592 CTAs (4/SM) grid-stride over 4096
// blocks of 2 rows. Each block-iteration issues ALL 8 x-loads up front
// (4 col-groups x 2 rows), then drains group-by-group while the remaining
// groups stay in flight on the scoreboard.

#define TPB 256
#define RPB 2
#define COLS 4096
#define BATCH 8192
#define OUTS 8
#define NBLK (BATCH / RPB)   // 4096
#define GRID 592             // 4 CTAs per SM on 148 SMs

__global__ __launch_bounds__(TPB, 4)
void enn_kernel(const float* __restrict__ x,
                const float* __restrict__ w_in,
                const float* __restrict__ w_ho,
                const float* __restrict__ thr_h,
                float* __restrict__ out)
{
    __shared__ float s_part[8][RPB][3];  // [warp][row][hidden]
    __shared__ float s_base[OUTS];
    __shared__ float s_tanh[61];

    const int t    = threadIdx.x;
    const int warp = t >> 5;
    const int lane = t & 31;

    // ---- once per CTA: fold the 61 disconnected hiddens into base[o]
    if (t < 61)
        s_tanh[t] = tanhf(-thr_h[t + 3]);
    __syncthreads();
    if (t < OUTS) {
        float b = -0.5f;
        #pragma unroll
        for (int j = 0; j < 61; j++)
            b = fmaf(s_tanh[j], __ldg(w_ho + (j + 3) * OUTS + t), b);
        s_base[t] = b;
    }
    const float th0 = __ldg(thr_h + 0);
    const float th1 = __ldg(thr_h + 1);
    const float th2 = __ldg(thr_h + 2);

    // ---- persistent loop over row-blocks
    for (int blk = blockIdx.x; blk < NBLK; blk += GRID) {
        const size_t row0 = (size_t)blk * RPB;
        const float4* x0 = reinterpret_cast<const float4*>(x + row0 * COLS);
        const float4* x1 = reinterpret_cast<const float4*>(x + (row0 + 1) * COLS);

        // issue ALL 8 x loads for this block up front (max in-flight depth)
        float4 xv[4][RPB];
        #pragma unroll
        for (int c = 0; c < 4; c++) {
            xv[c][0] = __ldcs(x0 + c * 256 + t);
            xv[c][1] = __ldcs(x1 + c * 256 + t);
        }

        float acc[RPB][3];
        #pragma unroll
        for (int r = 0; r < RPB; r++) {
            acc[r][0] = 0.f; acc[r][1] = 0.f; acc[r][2] = 0.f;
        }

        #pragma unroll
        for (int c = 0; c < 4; c++) {
            // 12-float w group for columns {c*1024 + 4t .. +3}  (L1/L2-hot)
            const float4* wp = reinterpret_cast<const float4*>(
                w_in + ((size_t)(c * 1024) + t * 4) * 3);
            const float4 w0 = __ldg(wp + 0);
            const float4 w1 = __ldg(wp + 1);
            const float4 w2 = __ldg(wp + 2);

            #pragma unroll
            for (int r = 0; r < RPB; r++) {
                const float4 v = xv[c][r];
                // element e of the 12-float group -> (col + e/3, hidden e%3)
                acc[r][0] = fmaf(v.x, w0.x, acc[r][0]);
                acc[r][1] = fmaf(v.x, w0.y, acc[r][1]);
                acc[r][2] = fmaf(v.x, w0.z, acc[r][2]);
                acc[r][0] = fmaf(v.y, w0.w, acc[r][0]);
                acc[r][1] = fmaf(v.y, w1.x, acc[r][1]);
                acc[r][2] = fmaf(v.y, w1.y, acc[r][2]);
                acc[r][0] = fmaf(v.z, w1.z, acc[r][0]);
                acc[r][1] = fmaf(v.z, w1.w, acc[r][1]);
                acc[r][2] = fmaf(v.z, w2.x, acc[r][2]);
                acc[r][0] = fmaf(v.w, w2.y, acc[r][0]);
                acc[r][1] = fmaf(v.w, w2.z, acc[r][1]);
                acc[r][2] = fmaf(v.w, w2.w, acc[r][2]);
            }
        }

        // butterfly reduce the 6 accumulators across the warp
        #pragma unroll
        for (int off = 16; off > 0; off >>= 1) {
            #pragma unroll
            for (int r = 0; r < RPB; r++) {
                acc[r][0] += __shfl_xor_sync(0xFFFFFFFFu, acc[r][0], off);
                acc[r][1] += __shfl_xor_sync(0xFFFFFFFFu, acc[r][1], off);
                acc[r][2] += __shfl_xor_sync(0xFFFFFFFFu, acc[r][2], off);
            }
        }
        if (lane == 0) {
            #pragma unroll
            for (int r = 0; r < RPB; r++) {
                s_part[warp][r][0] = acc[r][0];
                s_part[warp][r][1] = acc[r][1];
                s_part[warp][r][2] = acc[r][2];
            }
        }
        __syncthreads();

        // 16 threads: one (row, output) pair each
        if (t < RPB * OUTS) {
            const int r = t >> 3;
            const int o = t & 7;
            float s0 = 0.f, s1 = 0.f, s2 = 0.f;
            #pragma unroll
            for (int w = 0; w < 8; w++) {
                s0 += s_part[w][r][0];
                s1 += s_part[w][r][1];
                s2 += s_part[w][r][2];
            }
            const float h0 = tanhf(s0 - th0);
            const float h1 = tanhf(s1 - th1);
            const float h2 = tanhf(s2 - th2);
            float v = s_base[o];
            v = fmaf(h0, __ldg(w_ho + 0 * OUTS + o), v);
            v = fmaf(h1, __ldg(w_ho + 1 * OUTS + o), v);
            v = fmaf(h2, __ldg(w_ho + 2 * OUTS + o), v);
            out[(row0 + r) * OUTS + o] = tanhf(v);
        }
        __syncthreads();   // protect s_part before next block iteration
    }
}

extern "C" void kernel_launch(void* const* d_in, const int* in_sizes, int n_in,
                              void* d_out, int out_size)
{
    const float* x     = (const float*)d_in[0];
    const float* w_in  = (const float*)d_in[1];
    const float* w_ho  = (const float*)d_in[2];
    const float* thr_h = (const float*)d_in[3];
    float* out = (float*)d_out;

    enn_kernel<<<GRID, TPB>>>(x, w_in, w_ho, thr_h, out);
}

// round 15
// speedup vs baseline: 1.8530x; 1.2116x over previous
#include <cuda_runtime.h>

// EmergentNeuralNetwork collapsed form: out = tanh(h_star @ w_ho - 0.5)
//   h_star[:, j<3]  = tanh(x @ w_in[:, j] - thr_h[j])
//   h_star[:, j>=3] = tanh(-thr_h[j])  (batch-constant, folded once per CTA)
//
// Inputs: x f32[8192,4096], w_in f32[4096,3], w_ho f32[64,8], thr_h f32[64]
// Output: f32[8192,8]
//
// Hybrid w staging, NO cudaFuncSetAttribute (dynamic smem 36 KB < default
// budget -> plain launch path). Groups c=0..2 of w_in live in SMEM
// (element-major, conflict-free LDS.128); group c=3 stays LDG but is issued
// BEFORE the x loads so its in-order FIFO completion isn't gated behind the
// 8 DRAM misses. Persistent 592 CTAs (4/SM), RPB=2.

#define TPB 256
#define RPB 2
#define COLS 4096
#define BATCH 8192
#define OUTS 8
#define NBLK (BATCH / RPB)     // 4096
#define GRID 592               // 4 CTAs per SM on 148 SMs
#define WG_SMEM 3              // w groups staged in smem (c = 0..2)
#define W_SMEM_BYTES (WG_SMEM * 3 * TPB * 16)   // 36864 B

__global__ __launch_bounds__(TPB, 4)
void enn_kernel(const float* __restrict__ x,
                const float* __restrict__ w_in,
                const float* __restrict__ w_ho,
                const float* __restrict__ thr_h,
                float* __restrict__ out)
{
    extern __shared__ float4 s_w4[];     // [WG_SMEM][3][TPB] = 36 KB
    __shared__ float s_part[8][RPB][3];  // [warp][row][hidden]
    __shared__ float s_base[OUTS];
    __shared__ float s_tanh[61];

    const int t    = threadIdx.x;
    const int warp = t >> 5;
    const int lane = t & 31;

    // ---- once per CTA: stage w groups 0..2 into smem, element-major.
    // thread t's group-c chunk: 48 contiguous bytes at w_in[(c*1024+4t)*3].
    #pragma unroll
    for (int c = 0; c < WG_SMEM; c++) {
        const float4* wp = reinterpret_cast<const float4*>(
            w_in + ((size_t)(c * 1024) + t * 4) * 3);
        s_w4[(c * 3 + 0) * TPB + t] = __ldg(wp + 0);
        s_w4[(c * 3 + 1) * TPB + t] = __ldg(wp + 1);
        s_w4[(c * 3 + 2) * TPB + t] = __ldg(wp + 2);
    }

    // ---- once per CTA: fold the 61 disconnected hiddens into base[o]
    if (t < 61)
        s_tanh[t] = tanhf(-thr_h[t + 3]);
    __syncthreads();
    if (t < OUTS) {
        float b = -0.5f;
        #pragma unroll
        for (int j = 0; j < 61; j++)
            b = fmaf(s_tanh[j], __ldg(w_ho + (j + 3) * OUTS + t), b);
        s_base[t] = b;
    }
    const float th0 = __ldg(thr_h + 0);
    const float th1 = __ldg(thr_h + 1);
    const float th2 = __ldg(thr_h + 2);

    // group-3 w pointer (reused every iteration; L1/L2-hot)
    const float4* wp3 = reinterpret_cast<const float4*>(
        w_in + ((size_t)(3 * 1024) + t * 4) * 3);

    // ---- persistent loop over row-blocks
    for (int blk = blockIdx.x; blk < NBLK; blk += GRID) {
        const size_t row0 = (size_t)blk * RPB;
        const float4* x0 = reinterpret_cast<const float4*>(x + row0 * COLS);
        const float4* x1 = reinterpret_cast<const float4*>(x + (row0 + 1) * COLS);

        // issue group-3 w loads FIRST (L1 hits complete at hit latency,
        // not behind the x misses in the in-order L1tex FIFO) ...
        const float4 g3w0 = __ldg(wp3 + 0);
        const float4 g3w1 = __ldg(wp3 + 1);
        const float4 g3w2 = __ldg(wp3 + 2);

        // ... then ALL 8 x loads (the only DRAM misses in the FIFO)
        float4 xv[4][RPB];
        #pragma unroll
        for (int c = 0; c < 4; c++) {
            xv[c][0] = __ldcs(x0 + c * 256 + t);
            xv[c][1] = __ldcs(x1 + c * 256 + t);
        }

        float acc[RPB][3];
        #pragma unroll
        for (int r = 0; r < RPB; r++) {
            acc[r][0] = 0.f; acc[r][1] = 0.f; acc[r][2] = 0.f;
        }

        #pragma unroll
        for (int c = 0; c < 4; c++) {
            // groups 0..2 from smem (LDS.128, fixed ~29 cyc); group 3 from regs
            const float4 w0 = (c < WG_SMEM) ? s_w4[(c * 3 + 0) * TPB + t] : g3w0;
            const float4 w1 = (c < WG_SMEM) ? s_w4[(c * 3 + 1) * TPB + t] : g3w1;
            const float4 w2 = (c < WG_SMEM) ? s_w4[(c * 3 + 2) * TPB + t] : g3w2;

            #pragma unroll
            for (int r = 0; r < RPB; r++) {
                const float4 v = xv[c][r];
                // element e of the 12-float group -> (col + e/3, hidden e%3)
                acc[r][0] = fmaf(v.x, w0.x, acc[r][0]);
                acc[r][1] = fmaf(v.x, w0.y, acc[r][1]);
                acc[r][2] = fmaf(v.x, w0.z, acc[r][2]);
                acc[r][0] = fmaf(v.y, w0.w, acc[r][0]);
                acc[r][1] = fmaf(v.y, w1.x, acc[r][1]);
                acc[r][2] = fmaf(v.y, w1.y, acc[r][2]);
                acc[r][0] = fmaf(v.z, w1.z, acc[r][0]);
                acc[r][1] = fmaf(v.z, w1.w, acc[r][1]);
                acc[r][2] = fmaf(v.z, w2.x, acc[r][2]);
                acc[r][0] = fmaf(v.w, w2.y, acc[r][0]);
                acc[r][1] = fmaf(v.w, w2.z, acc[r][1]);
                acc[r][2] = fmaf(v.w, w2.w, acc[r][2]);
            }
        }

        // butterfly reduce the 6 accumulators across the warp
        #pragma unroll
        for (int off = 16; off > 0; off >>= 1) {
            #pragma unroll
            for (int r = 0; r < RPB; r++) {
                acc[r][0] += __shfl_xor_sync(0xFFFFFFFFu, acc[r][0], off);
                acc[r][1] += __shfl_xor_sync(0xFFFFFFFFu, acc[r][1], off);
                acc[r][2] += __shfl_xor_sync(0xFFFFFFFFu, acc[r][2], off);
            }
        }
        if (lane == 0) {
            #pragma unroll
            for (int r = 0; r < RPB; r++) {
                s_part[warp][r][0] = acc[r][0];
                s_part[warp][r][1] = acc[r][1];
                s_part[warp][r][2] = acc[r][2];
            }
        }
        __syncthreads();

        // 16 threads: one (row, output) pair each
        if (t < RPB * OUTS) {
            const int r = t >> 3;
            const int o = t & 7;
            float s0 = 0.f, s1 = 0.f, s2 = 0.f;
            #pragma unroll
            for (int w = 0; w < 8; w++) {
                s0 += s_part[w][r][0];
                s1 += s_part[w][r][1];
                s2 += s_part[w][r][2];
            }
            const float h0 = tanhf(s0 - th0);
            const float h1 = tanhf(s1 - th1);
            const float h2 = tanhf(s2 - th2);
            float v = s_base[o];
            v = fmaf(h0, __ldg(w_ho + 0 * OUTS + o), v);
            v = fmaf(h1, __ldg(w_ho + 1 * OUTS + o), v);
            v = fmaf(h2, __ldg(w_ho + 2 * OUTS + o), v);
            out[(row0 + r) * OUTS + o] = tanhf(v);
        }
        __syncthreads();   // protect s_part before next block iteration
    }
}

extern "C" void kernel_launch(void* const* d_in, const int* in_sizes, int n_in,
                              void* d_out, int out_size)
{
    const float* x     = (const float*)d_in[0];
    const float* w_in  = (const float*)d_in[1];
    const float* w_ho  = (const float*)d_in[2];
    const float* thr_h = (const float*)d_in[3];
    float* out = (float*)d_out;

    // 36 KB dynamic + ~1 KB static < 48 KB default budget: plain launch,
    // no attribute call.
    enn_kernel<<<GRID, TPB, W_SMEM_BYTES>>>(x, w_in, w_ho, thr_h, out);
}

// round 16
// speedup vs baseline: 1.8551x; 1.0011x over previous
#include <cuda_runtime.h>

// EmergentNeuralNetwork collapsed form: out = tanh(h_star @ w_ho - 0.5)
//   h_star[:, j<3]  = tanh(x @ w_in[:, j] - thr_h[j])
//   h_star[:, j>=3] = tanh(-thr_h[j])  (batch-constant, folded once per CTA)
//
// Inputs: x f32[8192,4096], w_in f32[4096,3], w_ho f32[64,8], thr_h f32[64]
// Output: f32[8192,8]
//
// R16: cross-iteration rotating load pipeline. As group c's xv regs are
// consumed, they are immediately reloaded with the NEXT block's group-c
// data, so all 8 loads of iteration n+1 are in flight during iteration n's
// reduction tail. One barrier per iteration (parity-buffered s_part).
// w groups 0..2 in smem (conflict-free LDS.128); group 3 via L1-hot LDG
// issued at iteration top. Persistent 592 CTAs (4/SM), RPB=2, 36 KB smem
// (< default budget -> plain launch, no attribute call).

#define TPB 256
#define RPB 2
#define COLS 4096
#define BATCH 8192
#define OUTS 8
#define NBLK (BATCH / RPB)     // 4096
#define GRID 592               // 4 CTAs per SM on 148 SMs
#define WG_SMEM 3              // w groups staged in smem (c = 0..2)
#define W_SMEM_BYTES (WG_SMEM * 3 * TPB * 16)   // 36864 B

__global__ __launch_bounds__(TPB, 4)
void enn_kernel(const float* __restrict__ x,
                const float* __restrict__ w_in,
                const float* __restrict__ w_ho,
                const float* __restrict__ thr_h,
                float* __restrict__ out)
{
    extern __shared__ float4 s_w4[];        // [WG_SMEM][3][TPB] = 36 KB
    __shared__ float s_part[2][8][RPB][3];  // parity-buffered [warp][row][hid]
    __shared__ float s_base[OUTS];
    __shared__ float s_tanh[61];

    const int t    = threadIdx.x;
    const int warp = t >> 5;
    const int lane = t & 31;

    // ---- once per CTA: stage w groups 0..2 into smem, element-major.
    #pragma unroll
    for (int c = 0; c < WG_SMEM; c++) {
        const float4* wp = reinterpret_cast<const float4*>(
            w_in + ((size_t)(c * 1024) + t * 4) * 3);
        s_w4[(c * 3 + 0) * TPB + t] = __ldg(wp + 0);
        s_w4[(c * 3 + 1) * TPB + t] = __ldg(wp + 1);
        s_w4[(c * 3 + 2) * TPB + t] = __ldg(wp + 2);
    }

    // ---- once per CTA: fold the 61 disconnected hiddens into base[o]
    if (t < 61)
        s_tanh[t] = tanhf(-thr_h[t + 3]);
    __syncthreads();
    if (t < OUTS) {
        float b = -0.5f;
        #pragma unroll
        for (int j = 0; j < 61; j++)
            b = fmaf(s_tanh[j], __ldg(w_ho + (j + 3) * OUTS + t), b);
        s_base[t] = b;
    }
    const float th0 = __ldg(thr_h + 0);
    const float th1 = __ldg(thr_h + 1);
    const float th2 = __ldg(thr_h + 2);

    // group-3 w pointer (reused every iteration; L1/L2-hot)
    const float4* wp3 = reinterpret_cast<const float4*>(
        w_in + ((size_t)(3 * 1024) + t * 4) * 3);

    // ---- prologue: load the first block's 8 x tiles
    float4 xv[4][RPB];
    {
        const size_t row0 = (size_t)blockIdx.x * RPB;
        const float4* x0 = reinterpret_cast<const float4*>(x + row0 * COLS);
        const float4* x1 = reinterpret_cast<const float4*>(x + (row0 + 1) * COLS);
        #pragma unroll
        for (int c = 0; c < 4; c++) {
            xv[c][0] = __ldcs(x0 + c * 256 + t);
            xv[c][1] = __ldcs(x1 + c * 256 + t);
        }
    }

    int parity = 0;
    for (int blk = blockIdx.x; blk < NBLK; blk += GRID, parity ^= 1) {
        const size_t row0 = (size_t)blk * RPB;
        // next block (clamped: final iteration harmlessly reloads itself)
        const int nblk = (blk + GRID < NBLK) ? (blk + GRID) : blk;
        const size_t nrow0 = (size_t)nblk * RPB;
        const float4* n0 = reinterpret_cast<const float4*>(x + nrow0 * COLS);
        const float4* n1 = reinterpret_cast<const float4*>(x + (nrow0 + 1) * COLS);

        // L1-hot group-3 w loads, issued ahead of their c=3 use
        const float4 g3w0 = __ldg(wp3 + 0);
        const float4 g3w1 = __ldg(wp3 + 1);
        const float4 g3w2 = __ldg(wp3 + 2);

        float acc[RPB][3];
        #pragma unroll
        for (int r = 0; r < RPB; r++) {
            acc[r][0] = 0.f; acc[r][1] = 0.f; acc[r][2] = 0.f;
        }

        #pragma unroll
        for (int c = 0; c < 4; c++) {
            // w: groups 0..2 from smem (fixed ~29 cyc), group 3 from regs
            const float4 w0 = (c < WG_SMEM) ? s_w4[(c * 3 + 0) * TPB + t] : g3w0;
            const float4 w1 = (c < WG_SMEM) ? s_w4[(c * 3 + 1) * TPB + t] : g3w1;
            const float4 w2 = (c < WG_SMEM) ? s_w4[(c * 3 + 2) * TPB + t] : g3w2;

            // consume current values into locals, then immediately reload
            // xv[c] with the NEXT block's tile (stays in flight through the
            // reduction tail and the barrier)
            const float4 v0 = xv[c][0];
            const float4 v1 = xv[c][1];
            xv[c][0] = __ldcs(n0 + c * 256 + t);
            xv[c][1] = __ldcs(n1 + c * 256 + t);

            // element e of the 12-float w group -> (col + e/3, hidden e%3)
            acc[0][0] = fmaf(v0.x, w0.x, acc[0][0]);
            acc[0][1] = fmaf(v0.x, w0.y, acc[0][1]);
            acc[0][2] = fmaf(v0.x, w0.z, acc[0][2]);
            acc[0][0] = fmaf(v0.y, w0.w, acc[0][0]);
            acc[0][1] = fmaf(v0.y, w1.x, acc[0][1]);
            acc[0][2] = fmaf(v0.y, w1.y, acc[0][2]);
            acc[0][0] = fmaf(v0.z, w1.z, acc[0][0]);
            acc[0][1] = fmaf(v0.z, w1.w, acc[0][1]);
            acc[0][2] = fmaf(v0.z, w2.x, acc[0][2]);
            acc[0][0] = fmaf(v0.w, w2.y, acc[0][0]);
            acc[0][1] = fmaf(v0.w, w2.z, acc[0][1]);
            acc[0][2] = fmaf(v0.w, w2.w, acc[0][2]);

            acc[1][0] = fmaf(v1.x, w0.x, acc[1][0]);
            acc[1][1] = fmaf(v1.x, w0.y, acc[1][1]);
            acc[1][2] = fmaf(v1.x, w0.z, acc[1][2]);
            acc[1][0] = fmaf(v1.y, w0.w, acc[1][0]);
            acc[1][1] = fmaf(v1.y, w1.x, acc[1][1]);
            acc[1][2] = fmaf(v1.y, w1.y, acc[1][2]);
            acc[1][0] = fmaf(v1.z, w1.z, acc[1][0]);
            acc[1][1] = fmaf(v1.z, w1.w, acc[1][1]);
            acc[1][2] = fmaf(v1.z, w2.x, acc[1][2]);
            acc[1][0] = fmaf(v1.w, w2.y, acc[1][0]);
            acc[1][1] = fmaf(v1.w, w2.z, acc[1][1]);
            acc[1][2] = fmaf(v1.w, w2.w, acc[1][2]);
        }

        // butterfly reduce the 6 accumulators across the warp
        #pragma unroll
        for (int off = 16; off > 0; off >>= 1) {
            #pragma unroll
            for (int r = 0; r < RPB; r++) {
                acc[r][0] += __shfl_xor_sync(0xFFFFFFFFu, acc[r][0], off);
                acc[r][1] += __shfl_xor_sync(0xFFFFFFFFu, acc[r][1], off);
                acc[r][2] += __shfl_xor_sync(0xFFFFFFFFu, acc[r][2], off);
            }
        }
        if (lane == 0) {
            #pragma unroll
            for (int r = 0; r < RPB; r++) {
                s_part[parity][warp][r][0] = acc[r][0];
                s_part[parity][warp][r][1] = acc[r][1];
                s_part[parity][warp][r][2] = acc[r][2];
            }
        }
        // single barrier per iteration: orders this parity's writes before
        // its reads, AND last iteration's reads before its slot is reused.
        __syncthreads();

        // 16 threads: one (row, output) pair each
        if (t < RPB * OUTS) {
            const int r = t >> 3;
            const int o = t & 7;
            float s0 = 0.f, s1 = 0.f, s2 = 0.f;
            #pragma unroll
            for (int w = 0; w < 8; w++) {
                s0 += s_part[parity][w][r][0];
                s1 += s_part[parity][w][r][1];
                s2 += s_part[parity][w][r][2];
            }
            const float h0 = tanhf(s0 - th0);
            const float h1 = tanhf(s1 - th1);
            const float h2 = tanhf(s2 - th2);
            float v = s_base[o];
            v = fmaf(h0, __ldg(w_ho + 0 * OUTS + o), v);
            v = fmaf(h1, __ldg(w_ho + 1 * OUTS + o), v);
            v = fmaf(h2, __ldg(w_ho + 2 * OUTS + o), v);
            out[(row0 + r) * OUTS + o] = tanhf(v);
        }
    }
}

extern "C" void kernel_launch(void* const* d_in, const int* in_sizes, int n_in,
                              void* d_out, int out_size)
{
    const float* x     = (const float*)d_in[0];
    const float* w_in  = (const float*)d_in[1];
    const float* w_ho  = (const float*)d_in[2];
    const float* thr_h = (const float*)d_in[3];
    float* out = (float*)d_out;

    // 36 KB dynamic + ~1.5 KB static < 48 KB default budget: plain launch.
    enn_kernel<<<GRID, TPB, W_SMEM_BYTES>>>(x, w_in, w_ho, thr_h, out);
}